// round 9
// baseline (speedup 1.0000x reference)
#include <cuda_runtime.h>
#include <math.h>
#include <stdint.h>

#define NF 5
#define D 64
#define NHID 128
#define H 8192     /* D*NHID */
#define BATCH 4096
#define BM 32
#define NTH 512

#define XP   132   /* xs (dup'd) pitch: 64*2 + 4 */
#define W1P  132   /* w1t row pitch per kc: 64*2 + 4 */
#define W2P  516   /* w2t row pitch per ocq: 128*4 + 4 */
#define TSP  132   /* ts/ps pitch: 128 + 4 */

// Precomputed, batch-independent:
__device__ float g_wn1p[NF * D * 64 * 128];  // [f][i][kc][j][2] = (w[kc][j], w[kc+64][j])
__device__ float g_wn2p[NF * D * 16 * 512];  // [f][i][ocq][k][4] = u_{ocq*4+0..3}[k]
__device__ float g_c[NF * D * 64 * 2];       // [f][i][kc][2] = wpl diag pairs
__device__ float g_b1p[NF * D * 64 * 2];     // [f][i][kc][2] = (b1[kc], b1[kc+64])

__device__ __forceinline__ float fast_sp(float z) {
    return fmaxf(z, 0.f) + __logf(1.f + __expf(-fabsf(z)));
}
__device__ __forceinline__ unsigned long long pk2(float lo, float hi) {
    unsigned long long r;
    asm("mov.b64 %0,{%1,%2};" : "=l"(r) : "f"(lo), "f"(hi));
    return r;
}
__device__ __forceinline__ void upk2(unsigned long long v, float& lo, float& hi) {
    asm("mov.b64 {%0,%1},%2;" : "=f"(lo), "=f"(hi) : "l"(v));
}
__device__ __forceinline__ unsigned long long ffma2(unsigned long long a,
                                                    unsigned long long b,
                                                    unsigned long long c) {
    unsigned long long d;
    asm("fma.rn.f32x2 %0,%1,%2,%3;" : "=l"(d) : "l"(a), "l"(b), "l"(c));
    return d;
}

// ---------------------------------------------------------------------------
__global__ void prep1(const float* __restrict__ W1, const float* __restrict__ d1) {
    int idx = blockIdx.x * blockDim.x + threadIdx.x;
    if (idx >= NF * H) return;
    int f = idx / H, r = idx % H;
    int i = r >> 7, k = r & 127;
    const float* Wrow = W1 + (size_t)(f * H + r) * D;
    float dv = d1[f * H + r];
    float wdiag = expf(Wrow[i]);
    float wsn = wdiag * wdiag;
    for (int j = 0; j < i; j++) { float wv = Wrow[j]; wsn += wv * wv; }
    float scale = expf(dv) * rsqrtf(wsn);
    float* dst = g_wn1p + ((size_t)(f * D + i) * 64 + (k & 63)) * 128 + (k >> 6);
    for (int j = 0; j < D; j++) {
        float wv = (j < i) ? Wrow[j] : ((j == i) ? wdiag : 0.f);
        dst[j * 2] = wv * scale;
    }
    g_c[((f * D + i) * 64 + (k & 63)) * 2 + (k >> 6)] = dv + Wrow[i] - 0.5f * logf(wsn);
}

// ---------------------------------------------------------------------------
__global__ void prep2(const float* __restrict__ W2, const float* __restrict__ d2) {
    int f = blockIdx.x >> 6;
    int oc = blockIdx.x & 63;
    int tid = threadIdx.x;
    const float* Wrow = W2 + (size_t)(f * D + oc) * H;
    __shared__ float red[128];
    float wsn = 0.f;
    int lim = (oc + 1) * NHID;
    for (int j = tid; j < lim; j += 128) {
        int jb = j >> 7;
        float wv = (jb == oc) ? expf(Wrow[j]) : Wrow[j];
        wsn += wv * wv;
    }
    red[tid] = wsn;
    __syncthreads();
    for (int s = 64; s > 0; s >>= 1) {
        if (tid < s) red[tid] += red[tid + s];
        __syncthreads();
    }
    wsn = red[0];
    float dv = d2[f * D + oc];
    float scale = expf(dv) * rsqrtf(wsn);
    for (int j = tid; j < H; j += 128) {
        int jb = j >> 7, k = j & 127;
        float wv = (jb < oc) ? Wrow[j] : ((jb == oc) ? expf(Wrow[j]) : 0.f);
        g_wn2p[((size_t)(f * D + jb) * 16 + (oc >> 2)) * 512 + k * 4 + (oc & 3)] = wv * scale;
    }
    g_c[((f * D + oc) * 64 + (tid & 63)) * 2 + (tid >> 6)] +=
        dv + Wrow[oc * NHID + tid] - 0.5f * logf(wsn);
}

// pack b1 into pairs (b1[kc], b1[kc+64]) per (f, i)
__global__ void prep3(const float* __restrict__ b1) {
    int idx = blockIdx.x * blockDim.x + threadIdx.x;
    if (idx >= NF * H) return;
    int f = idx / H, r = idx % H;
    int i = r >> 7, k = r & 127;
    g_b1p[((f * D + i) * 64 + (k & 63)) * 2 + (k >> 6)] = b1[f * H + i * NHID + k];
}

// ---------------------------------------------------------------------------
// Main fused kernel: 128 CTAs x 512 threads, double-buffered weights,
// FFMA2 (fma.rn.f32x2) packed math in both GEMM phases.
// ---------------------------------------------------------------------------
__global__ void __launch_bounds__(NTH, 1) bnaf_main(
    const float* __restrict__ x, const float* __restrict__ b2,
    const float* __restrict__ gates, float* __restrict__ out)
{
    extern __shared__ float sm[];
    float* xs  = sm;                         // BM*XP      = 4224 (dup'd x)
    float* w1t = xs + BM * XP;               // 2*64*W1P   = 16896
    float* w2t = w1t + 2 * 64 * W1P;         // 2*16*W2P   = 16512
    float* ts  = w2t + 2 * 16 * W2P;         // BM*TSP     = 4224
    float* ps  = ts + BM * TSP;              // BM*TSP     = 4224
    float* lds_s = ps + BM * TSP;            // BM

    const int tid = threadIdx.x;
    const int b0 = blockIdx.x * BM;
    const float LN2 = 0.6931471805599453f;

    // phase1 mapping: kc = packed col pair (kc, kc+64), 4 rows
    const int kc = tid & 63;
    const int rb = (tid >> 6) * 4;
    // phase2 mapping: warp -> oc quad (SMSP-balanced), lane -> row
    const int wid = tid >> 5, lane = tid & 31;
    const int s_ = wid & 3, t_ = wid >> 2;
    const int gperm = ((t_ & 1) ? (7 - s_) : s_) + 8 * (t_ >> 1);
    const int oc0 = gperm * 4;
    // logsumexp mapping: 16 lanes per row
    const int lrow = tid >> 4, lsub = tid & 15;

    {   // load x tile -> duplicated layout
        int r = tid >> 4, c4 = tid & 15;
        float4 xv = *(const float4*)(x + (size_t)(b0 + r) * D + c4 * 4);
        float4 lo = make_float4(xv.x, xv.x, xv.y, xv.y);
        float4 hi = make_float4(xv.z, xv.z, xv.w, xv.w);
        *(float4*)(xs + r * XP + c4 * 8)     = lo;
        *(float4*)(xs + r * XP + c4 * 8 + 4) = hi;
    }
    if (tid < BM) lds_s[tid] = 0.f;

    // ---- prologue: stage tile g=0 into buffer 0 (i=0 -> 2 float4 per k row)
    {
        for (int q = tid; q < 64 * 32; q += NTH) {
            int k = q >> 5, c4 = q & 31;
            if (c4 < 2)
                *(float4*)(w1t + k * W1P + c4 * 4) =
                    *(const float4*)(g_wn1p + k * 128 + c4 * 4);
        }
        for (int q = tid; q < 16 * 128; q += NTH) {
            int ocq = q >> 7, c4 = q & 127;
            *(float4*)(w2t + ocq * W2P + c4 * 4) =
                *(const float4*)(g_wn2p + ocq * 512 + c4 * 4);
        }
    }
    __syncthreads();

    for (int f = 0; f < NF; f++) {
        const bool gated = (f < NF - 1);
        const float gate = gated ? gates[f] : 0.f;
        const float sg = gated ? (1.f / (1.f + __expf(-gate))) : 0.f;
        const float spg = gated ? fast_sp(gate) : 0.f;

        unsigned long long yp01 = pk2(b2[f * D + oc0],     b2[f * D + oc0 + 1]);
        unsigned long long yp23 = pk2(b2[f * D + oc0 + 2], b2[f * D + oc0 + 3]);

        for (int i = 0; i < D; i++) {
            const int g = f * D + i;
            const int buf = g & 1;
            const float* w1b = w1t + buf * (64 * W1P);
            const float* w2b = w2t + buf * (16 * W2P);

            // ---- phase 1: packed (h_kc, h_kc+64) for 4 rows, j<=i
            unsigned long long acc[4];
            {
                unsigned long long bp = *(const unsigned long long*)(g_b1p + (g * 64 + kc) * 2);
                #pragma unroll
                for (int rr = 0; rr < 4; rr++) acc[rr] = bp;
            }
            {
                const float* wa = w1b + kc * W1P;
                #pragma unroll 4
                for (int j = 0; j <= i; j += 4) {
                    ulonglong2 wp0 = *(const ulonglong2*)(wa + j * 2);      // j, j+1
                    ulonglong2 wp1 = *(const ulonglong2*)(wa + j * 2 + 4);  // j+2, j+3
                    #pragma unroll
                    for (int rr = 0; rr < 4; rr++) {
                        const float* xr = xs + (rb + rr) * XP;
                        ulonglong2 xd0 = *(const ulonglong2*)(xr + j * 2);
                        ulonglong2 xd1 = *(const ulonglong2*)(xr + j * 2 + 4);
                        acc[rr] = ffma2(xd0.x, wp0.x, acc[rr]);
                        acc[rr] = ffma2(xd0.y, wp0.y, acc[rr]);
                        acc[rr] = ffma2(xd1.x, wp1.x, acc[rr]);
                        acc[rr] = ffma2(xd1.y, wp1.y, acc[rr]);
                    }
                }
            }

            // ---- fast tanh + log(1-tanh^2): E = e^{-2|h|} shared
            {
                float ca, cb;
                upk2(*(const unsigned long long*)(g_c + (g * 64 + kc) * 2), ca, cb);
                #pragma unroll
                for (int rr = 0; rr < 4; rr++) {
                    int r = rb + rr;
                    float h0, h1;
                    upk2(acc[rr], h0, h1);
                    float ah0 = fabsf(h0), ah1 = fabsf(h1);
                    float E0 = __expf(-2.f * ah0);
                    float E1 = __expf(-2.f * ah1);
                    float t0 = copysignf(__fdividef(1.f - E0, 1.f + E0), h0);
                    float t1 = copysignf(__fdividef(1.f - E1, 1.f + E1), h1);
                    ts[r * TSP + kc]      = t0;
                    ts[r * TSP + kc + 64] = t1;
                    float l0 = 2.f * (LN2 - ah0 - __logf(1.f + E0));
                    float l1 = 2.f * (LN2 - ah1 - __logf(1.f + E1));
                    ps[r * TSP + kc]      = ca + l0;
                    ps[r * TSP + kc + 64] = cb + l1;
                }
            }

            // ---- stage next tile into the other buffer (overlaps above)
            if (g + 1 < NF * D) {
                int gn = g + 1;
                int in = gn & 63;
                int jl4x2 = ((in >> 2) + 1) * 2;
                const float* w1src = g_wn1p + (size_t)gn * 64 * 128;
                float* w1d = w1t + (buf ^ 1) * (64 * W1P);
                #pragma unroll
                for (int q = tid; q < 64 * 32; q += NTH) {
                    int k = q >> 5, c4 = q & 31;
                    if (c4 < jl4x2)
                        *(float4*)(w1d + k * W1P + c4 * 4) =
                            *(const float4*)(w1src + k * 128 + c4 * 4);
                }
                const float* w2src = g_wn2p + (size_t)gn * 16 * 512;
                float* w2d = w2t + (buf ^ 1) * (16 * W2P);
                #pragma unroll
                for (int q = tid; q < 16 * 128; q += NTH) {
                    int ocq = q >> 7, c4 = q & 127;
                    if (((ocq << 2) | 3) >= in)
                        *(float4*)(w2d + ocq * W2P + c4 * 4) =
                            *(const float4*)(w2src + ocq * 512 + c4 * 4);
                }
            }
            __syncthreads();

            // ---- per-row logsumexp over 128 (16 lanes/row)
            {
                const float* pr = ps + lrow * TSP;
                float mx = -1e30f;
                #pragma unroll
                for (int m = 0; m < 8; m++) mx = fmaxf(mx, pr[lsub + 16 * m]);
                #pragma unroll
                for (int o = 8; o > 0; o >>= 1)
                    mx = fmaxf(mx, __shfl_xor_sync(0xffffffffu, mx, o));
                float se = 0.f;
                #pragma unroll
                for (int m = 0; m < 8; m++) se += __expf(pr[lsub + 16 * m] - mx);
                #pragma unroll
                for (int o = 8; o > 0; o >>= 1)
                    se += __shfl_xor_sync(0xffffffffu, se, o);
                if (lsub == 0) {
                    float gg = mx + __logf(se);
                    lds_s[lrow] += gated ? (fast_sp(gg + gate) - spg) : gg;
                }
            }

            // ---- phase 2: packed oc pairs, exact triangular warp skip
            if (oc0 + 3 >= i) {
                const float* tr = ts + lane * TSP;
                const float* uq = w2b + gperm * W2P;
                #pragma unroll 8
                for (int k = 0; k < NHID; k += 4) {
                    float4 tv = *(const float4*)(tr + k);
                    ulonglong2 u0 = *(const ulonglong2*)(uq + (k + 0) * 4);
                    ulonglong2 u1 = *(const ulonglong2*)(uq + (k + 1) * 4);
                    ulonglong2 u2 = *(const ulonglong2*)(uq + (k + 2) * 4);
                    ulonglong2 u3 = *(const ulonglong2*)(uq + (k + 3) * 4);
                    unsigned long long tt;
                    tt = pk2(tv.x, tv.x);
                    yp01 = ffma2(tt, u0.x, yp01); yp23 = ffma2(tt, u0.y, yp23);
                    tt = pk2(tv.y, tv.y);
                    yp01 = ffma2(tt, u1.x, yp01); yp23 = ffma2(tt, u1.y, yp23);
                    tt = pk2(tv.z, tv.z);
                    yp01 = ffma2(tt, u2.x, yp01); yp23 = ffma2(tt, u2.y, yp23);
                    tt = pk2(tv.w, tv.w);
                    yp01 = ffma2(tt, u3.x, yp01); yp23 = ffma2(tt, u3.y, yp23);
                }
            }
            __syncthreads();
        }

        // ---- gate-combine + reverse (or final output)
        float y0, y1, y2, y3;
        upk2(yp01, y0, y1);
        upk2(yp23, y2, y3);
        if (gated) {
            float yv[4] = {y0, y1, y2, y3};
            float xo[4];
            #pragma unroll
            for (int u = 0; u < 4; u++) {
                float xv = xs[lane * XP + (oc0 + u) * 2];
                xo[u] = sg * yv[u] + (1.f - sg) * xv;
            }
            __syncthreads();
            #pragma unroll
            for (int u = 0; u < 4; u++)
                *(unsigned long long*)(xs + lane * XP + (63 - (oc0 + u)) * 2) =
                    pk2(xo[u], xo[u]);
            __syncthreads();
        } else {
            ps[lane * TSP + oc0 + 0] = y0;
            ps[lane * TSP + oc0 + 1] = y1;
            ps[lane * TSP + oc0 + 2] = y2;
            ps[lane * TSP + oc0 + 3] = y3;
            __syncthreads();
            int r = tid >> 4, c4 = tid & 15;
            *(float4*)(out + (size_t)(b0 + r) * D + c4 * 4) =
                *(const float4*)(ps + r * TSP + c4 * 4);
        }
    }

    if (tid < BM) out[(size_t)BATCH * D + b0 + tid] = lds_s[tid];
}

static const int SMEM_BYTES =
    (BM * XP + 2 * 64 * W1P + 2 * 16 * W2P + 2 * BM * TSP + BM) * 4;

extern "C" void kernel_launch(void* const* d_in, const int* in_sizes, int n_in,
                              void* d_out, int out_size) {
    const float* x  = (const float*)d_in[0];
    const float* W1 = (const float*)d_in[1];
    const float* d1 = (const float*)d_in[2];
    const float* b1 = (const float*)d_in[3];
    const float* W2 = (const float*)d_in[4];
    const float* d2 = (const float*)d_in[5];
    const float* b2 = (const float*)d_in[6];
    const float* gates = (const float*)d_in[7];
    float* out = (float*)d_out;

    prep1<<<(NF * H + 255) / 256, 256>>>(W1, d1);
    prep2<<<NF * D, 128>>>(W2, d2);
    prep3<<<(NF * H + 255) / 256, 256>>>(b1);

    cudaFuncSetAttribute(bnaf_main, cudaFuncAttributeMaxDynamicSharedMemorySize, SMEM_BYTES);
    bnaf_main<<<BATCH / BM, NTH, SMEM_BYTES>>>(x, b2, gates, out);
}

// round 11
// speedup vs baseline: 1.0622x; 1.0622x over previous
#include <cuda_runtime.h>
#include <math.h>
#include <stdint.h>

#define NF 5
#define D 64
#define NHID 128
#define H 8192     /* D*NHID */
#define BATCH 4096
#define BM 32
#define NTH 512

#define XP   68    /* xs pitch  (4-float aligned, 4-bank lane stride) */
#define W1P  68    /* w1 tile pitch per k-row */
#define W2P  132   /* w2 tile pitch per oc-row */
#define TSP  132   /* ts/ps pitch */

typedef unsigned long long ull;

// Precomputed, batch-independent (plain layouts, zeros folded):
__device__ float g_wn1[NF * D * NHID * D];   // [f][i][k][j], zeros j>i
__device__ float g_wn2[NF * D * D * NHID];   // [f][i][oc][k], zeros oc<i
__device__ float g_c[NF * D * NHID];         // [f][i][k] wpl diag sum

__device__ __forceinline__ float fast_sp(float z) {
    return fmaxf(z, 0.f) + __logf(1.f + __expf(-fabsf(z)));
}
__device__ __forceinline__ void upk2(ull v, float& lo, float& hi) {
    asm("mov.b64 {%0,%1},%2;" : "=f"(lo), "=f"(hi) : "l"(v));
}
__device__ __forceinline__ ull ffma2(ull a, ull b, ull c) {
    ull d;
    asm("fma.rn.f32x2 %0,%1,%2,%3;" : "=l"(d) : "l"(a), "l"(b), "l"(c));
    return d;
}

// ---------------------------------------------------------------------------
__global__ void prep1(const float* __restrict__ W1, const float* __restrict__ d1) {
    int idx = blockIdx.x * blockDim.x + threadIdx.x;
    if (idx >= NF * H) return;
    int f = idx / H, r = idx % H;
    int i = r >> 7, k = r & 127;
    const float* Wrow = W1 + (size_t)(f * H + r) * D;
    float dv = d1[f * H + r];
    float wdiag = expf(Wrow[i]);
    float wsn = wdiag * wdiag;
    for (int j = 0; j < i; j++) { float wv = Wrow[j]; wsn += wv * wv; }
    float scale = expf(dv) * rsqrtf(wsn);
    float* dst = g_wn1 + ((size_t)(f * D + i) * NHID + k) * D;
    for (int j = 0; j < D; j++) {
        float wv = (j < i) ? Wrow[j] : ((j == i) ? wdiag : 0.f);
        dst[j] = wv * scale;
    }
    g_c[(f * D + i) * NHID + k] = dv + Wrow[i] - 0.5f * logf(wsn);
}

// ---------------------------------------------------------------------------
__global__ void prep2(const float* __restrict__ W2, const float* __restrict__ d2) {
    int f = blockIdx.x >> 6;
    int oc = blockIdx.x & 63;
    int tid = threadIdx.x;
    const float* Wrow = W2 + (size_t)(f * D + oc) * H;
    __shared__ float red[128];
    float wsn = 0.f;
    int lim = (oc + 1) * NHID;
    for (int j = tid; j < lim; j += 128) {
        int jb = j >> 7;
        float wv = (jb == oc) ? expf(Wrow[j]) : Wrow[j];
        wsn += wv * wv;
    }
    red[tid] = wsn;
    __syncthreads();
    for (int s = 64; s > 0; s >>= 1) {
        if (tid < s) red[tid] += red[tid + s];
        __syncthreads();
    }
    wsn = red[0];
    float dv = d2[f * D + oc];
    float scale = expf(dv) * rsqrtf(wsn);
    for (int j = tid; j < H; j += 128) {
        int jb = j >> 7, k = j & 127;
        float wv = (jb < oc) ? Wrow[j] : ((jb == oc) ? expf(Wrow[j]) : 0.f);
        g_wn2[((size_t)(f * D + jb) * D + oc) * NHID + k] = wv * scale;
    }
    g_c[(f * D + oc) * NHID + tid] += dv + Wrow[oc * NHID + tid] - 0.5f * logf(wsn);
}

// ---------------------------------------------------------------------------
__device__ __forceinline__ void stage_tiles(
    int gn, float* w1d, float* w2d, float* bcd,
    const float* __restrict__ b1g, int tid)
{
    int inx = gn & 63;
    int jl4 = (inx >> 2) + 1;
    const float* w1src = g_wn1 + (size_t)gn * NHID * D;
    #pragma unroll
    for (int q = tid; q < NHID * 16; q += NTH) {
        int k = q >> 4, c4 = q & 15;
        if (c4 < jl4)
            *(float4*)(w1d + k * W1P + c4 * 4) =
                *(const float4*)(w1src + k * D + c4 * 4);
    }
    const float* w2src = g_wn2 + (size_t)gn * D * NHID;
    #pragma unroll
    for (int q = tid; q < D * 32; q += NTH) {
        int o = q >> 5, c4 = q & 31;
        if ((o | 7) >= inx)
            *(float4*)(w2d + o * W2P + c4 * 4) =
                *(const float4*)(w2src + o * NHID + c4 * 4);
    }
    if (tid < 64) {
        if (tid < 32)
            *(float4*)(bcd + tid * 4) =
                *(const float4*)(b1g + (size_t)(gn >> 6) * H + inx * NHID + tid * 4);
        else
            *(float4*)(bcd + tid * 4) =
                *(const float4*)(g_c + (size_t)gn * NHID + (tid - 32) * 4);
    }
}

// ---------------------------------------------------------------------------
// Main fused kernel. 128 CTAs x 512 threads. FFMA2 packed along the
// reduction axis (no layout duplication, no packs). Double-buffered tiles.
// Phase2: warps 0-7, each 32 rows x 8 uniform oc (octet-paired per SMSP).
// ---------------------------------------------------------------------------
__global__ void __launch_bounds__(NTH, 1) bnaf_main(
    const float* __restrict__ x, const float* __restrict__ b1g,
    const float* __restrict__ b2, const float* __restrict__ gates,
    float* __restrict__ out)
{
    extern __shared__ float sm[];
    float* xs  = sm;                         // BM*XP        = 2176
    float* w1t = xs + BM * XP;               // 2*128*W1P    = 17408
    float* w2t = w1t + 2 * NHID * W1P;       // 2*64*W2P     = 16896
    float* bc  = w2t + 2 * D * W2P;          // 2*256        = 512
    float* ts  = bc + 512;                   // BM*TSP       = 4224
    float* ps  = ts + BM * TSP;              // BM*TSP       = 4224
    float* lds_s = ps + BM * TSP;            // BM

    const int tid = threadIdx.x;
    const int b0 = blockIdx.x * BM;
    const float TWOLN2 = 1.3862943611198906f;

    // phase1 mapping: kc (cols kc, kc+64), 4 rows
    const int kc = tid & 63;
    const int rb = (tid >> 6) * 4;
    // phase2 mapping: warps 0-7 -> octet of 8 ocs; SMSP s gets octets {s,7-s}
    const int wid = tid >> 5, lane = tid & 31;
    const int octet = (wid < 4) ? wid : (11 - wid);
    const int oc0 = octet * 8;
    // logsumexp mapping: 16 lanes per row, 8 contiguous each
    const int lrow = tid >> 4, lsub = tid & 15;

    {   // load x tile
        int r = tid >> 4, c4 = tid & 15;
        *(float4*)(xs + r * XP + c4 * 4) =
            *(const float4*)(x + (size_t)(b0 + r) * D + c4 * 4);
    }
    if (tid < BM) lds_s[tid] = 0.f;

    stage_tiles(0, w1t, w2t, bc, b1g, tid);
    __syncthreads();

    for (int f = 0; f < NF; f++) {
        const bool gated = (f < NF - 1);
        const float gate = gated ? gates[f] : 0.f;
        const float sg = gated ? (1.f / (1.f + __expf(-gate))) : 0.f;
        const float spg = gated ? fast_sp(gate) : 0.f;

        ull yp[8];
        #pragma unroll
        for (int m = 0; m < 8; m++) yp[m] = 0ull;

        for (int i = 0; i < D; i++) {
            const int g = f * D + i;
            const int buf = g & 1;
            const float* w1b = w1t + buf * (NHID * W1P);
            const float* w2b = w2t + buf * (D * W2P);
            const float* bcb = bc + buf * 256;

            // ---- phase 1: j-pair-packed accumulation, j<=i (zeros staged past i)
            ull a0[4] = {0ull, 0ull, 0ull, 0ull};
            ull a1[4] = {0ull, 0ull, 0ull, 0ull};
            {
                const float* wa = w1b + kc * W1P;
                const float* wb = w1b + (kc + 64) * W1P;
                #pragma unroll 4
                for (int j = 0; j <= i; j += 4) {
                    ulonglong2 wpa = *(const ulonglong2*)(wa + j);
                    ulonglong2 wpb = *(const ulonglong2*)(wb + j);
                    #pragma unroll
                    for (int rr = 0; rr < 4; rr++) {
                        ulonglong2 xp = *(const ulonglong2*)(xs + (rb + rr) * XP + j);
                        a0[rr] = ffma2(xp.x, wpa.x, a0[rr]);
                        a0[rr] = ffma2(xp.y, wpa.y, a0[rr]);
                        a1[rr] = ffma2(xp.x, wpb.x, a1[rr]);
                        a1[rr] = ffma2(xp.y, wpb.y, a1[rr]);
                    }
                }
            }

            // ---- tanh + log(1-tanh^2) via E = e^{-2|h|}
            {
                float b1a = bcb[kc], b1b = bcb[kc + 64];
                float ca2 = bcb[128 + kc] + TWOLN2;
                float cb2 = bcb[128 + kc + 64] + TWOLN2;
                #pragma unroll
                for (int rr = 0; rr < 4; rr++) {
                    int r = rb + rr;
                    float l0, h0v, l1, h1v;
                    upk2(a0[rr], l0, h0v);
                    upk2(a1[rr], l1, h1v);
                    float h0 = l0 + h0v + b1a;
                    float h1 = l1 + h1v + b1b;
                    float ah0 = fabsf(h0), ah1 = fabsf(h1);
                    float E0 = __expf(-2.f * ah0);
                    float E1 = __expf(-2.f * ah1);
                    float t0 = copysignf(__fdividef(1.f - E0, 1.f + E0), h0);
                    float t1 = copysignf(__fdividef(1.f - E1, 1.f + E1), h1);
                    ts[r * TSP + kc]      = t0;
                    ts[r * TSP + kc + 64] = t1;
                    float lg0 = __logf(1.f + E0);
                    float lg1 = __logf(1.f + E1);
                    ps[r * TSP + kc]      = fmaf(-2.f, ah0 + lg0, ca2);
                    ps[r * TSP + kc + 64] = fmaf(-2.f, ah1 + lg1, cb2);
                }
            }

            // ---- stage next tile into the other buffer (overlaps above)
            if (g + 1 < NF * D)
                stage_tiles(g + 1,
                            w1t + (buf ^ 1) * (NHID * W1P),
                            w2t + (buf ^ 1) * (D * W2P),
                            bc + (buf ^ 1) * 256, b1g, tid);
            __syncthreads();

            // ---- per-row logsumexp over 128 (16 lanes x 8 contiguous, regs reused)
            {
                const float* pr = ps + lrow * TSP + lsub * 8;
                float4 v0 = *(const float4*)(pr);
                float4 v1 = *(const float4*)(pr + 4);
                float mx = fmaxf(fmaxf(fmaxf(v0.x, v0.y), fmaxf(v0.z, v0.w)),
                                 fmaxf(fmaxf(v1.x, v1.y), fmaxf(v1.z, v1.w)));
                #pragma unroll
                for (int o = 8; o > 0; o >>= 1)
                    mx = fmaxf(mx, __shfl_xor_sync(0xffffffffu, mx, o));
                float se = __expf(v0.x - mx) + __expf(v0.y - mx)
                         + __expf(v0.z - mx) + __expf(v0.w - mx)
                         + __expf(v1.x - mx) + __expf(v1.y - mx)
                         + __expf(v1.z - mx) + __expf(v1.w - mx);
                #pragma unroll
                for (int o = 8; o > 0; o >>= 1)
                    se += __shfl_xor_sync(0xffffffffu, se, o);
                if (lsub == 0) {
                    float gg = mx + __logf(se);
                    lds_s[lrow] += gated ? (fast_sp(gg + gate) - spg) : gg;
                }
            }

            // ---- phase 2: warps 0-7, k-pair-packed, exact octet skip
            if (wid < 8 && oc0 + 7 >= i) {
                const float* tr = ts + lane * TSP;
                const float* uq = w2b + oc0 * W2P;
                #pragma unroll 4
                for (int k = 0; k < NHID; k += 4) {
                    ulonglong2 tp = *(const ulonglong2*)(tr + k);
                    #pragma unroll
                    for (int m = 0; m < 8; m++) {
                        ulonglong2 q = *(const ulonglong2*)(uq + m * W2P + k);
                        yp[m] = ffma2(tp.x, q.x, yp[m]);
                        yp[m] = ffma2(tp.y, q.y, yp[m]);
                    }
                }
            }
            __syncthreads();
        }

        // ---- gate-combine + reverse (or final output)
        if (gated) {
            float xo[8];
            if (wid < 8) {
                #pragma unroll
                for (int m = 0; m < 8; m++) {
                    float lo, hi;
                    upk2(yp[m], lo, hi);
                    float y = lo + hi + b2[f * D + oc0 + m];
                    float xv = xs[lane * XP + oc0 + m];
                    xo[m] = sg * y + (1.f - sg) * xv;
                }
            }
            __syncthreads();
            if (wid < 8) {
                #pragma unroll
                for (int m = 0; m < 8; m++)
                    xs[lane * XP + 63 - (oc0 + m)] = xo[m];
            }
            __syncthreads();
        } else {
            if (wid < 8) {
                #pragma unroll
                for (int m = 0; m < 8; m++) {
                    float lo, hi;
                    upk2(yp[m], lo, hi);
                    ps[lane * TSP + oc0 + m] = lo + hi + b2[f * D + oc0 + m];
                }
            }
            __syncthreads();
            int r = tid >> 4, c4 = tid & 15;
            *(float4*)(out + (size_t)(b0 + r) * D + c4 * 4) =
                *(const float4*)(ps + r * TSP + c4 * 4);
        }
    }

    if (tid < BM) out[(size_t)BATCH * D + b0 + tid] = lds_s[tid];
}

static const int SMEM_BYTES =
    (BM * XP + 2 * NHID * W1P + 2 * D * W2P + 512 + 2 * BM * TSP + BM) * 4;

extern "C" void kernel_launch(void* const* d_in, const int* in_sizes, int n_in,
                              void* d_out, int out_size) {
    const float* x  = (const float*)d_in[0];
    const float* W1 = (const float*)d_in[1];
    const float* d1 = (const float*)d_in[2];
    const float* b1 = (const float*)d_in[3];
    const float* W2 = (const float*)d_in[4];
    const float* d2 = (const float*)d_in[5];
    const float* b2 = (const float*)d_in[6];
    const float* gates = (const float*)d_in[7];
    float* out = (float*)d_out;

    prep1<<<(NF * H + 255) / 256, 256>>>(W1, d1);
    prep2<<<NF * D, 128>>>(W2, d2);

    cudaFuncSetAttribute(bnaf_main, cudaFuncAttributeMaxDynamicSharedMemorySize, SMEM_BYTES);
    bnaf_main<<<BATCH / BM, NTH, SMEM_BYTES>>>(x, b1, b2, gates, out);
}

// round 12
// speedup vs baseline: 1.0928x; 1.0287x over previous
#include <cuda_runtime.h>
#include <math.h>
#include <stdint.h>

#define NF 5
#define D 64
#define NHID 128
#define H 8192     /* D*NHID */
#define BATCH 4096
#define BM 32
#define NTH 512

#define XP   68    /* xs pitch */
#define W1P  68    /* w1 tile pitch per k-row */
#define W2P  136   /* w2 tile pitch per oc-row (staggered k-halves) */
#define TSP  132   /* ts/ps pitch */

typedef unsigned long long ull;

// Precomputed, batch-independent (plain layouts, zeros folded):
__device__ float g_wn1[NF * D * NHID * D];   // [f][i][k][j], zeros j>i
__device__ float g_wn2[NF * D * D * NHID];   // [f][i][oc][k], zeros oc<i
__device__ float g_c[NF * D * NHID];         // [f][i][k] wpl diag sum

__device__ __forceinline__ float fast_sp(float z) {
    return fmaxf(z, 0.f) + __logf(1.f + __expf(-fabsf(z)));
}
__device__ __forceinline__ void upk2(ull v, float& lo, float& hi) {
    asm("mov.b64 {%0,%1},%2;" : "=f"(lo), "=f"(hi) : "l"(v));
}
__device__ __forceinline__ ull ffma2(ull a, ull b, ull c) {
    ull d;
    asm("fma.rn.f32x2 %0,%1,%2,%3;" : "=l"(d) : "l"(a), "l"(b), "l"(c));
    return d;
}

// ---------------------------------------------------------------------------
__global__ void prep1(const float* __restrict__ W1, const float* __restrict__ d1) {
    int idx = blockIdx.x * blockDim.x + threadIdx.x;
    if (idx >= NF * H) return;
    int f = idx / H, r = idx % H;
    int i = r >> 7, k = r & 127;
    const float* Wrow = W1 + (size_t)(f * H + r) * D;
    float dv = d1[f * H + r];
    float wdiag = expf(Wrow[i]);
    float wsn = wdiag * wdiag;
    for (int j = 0; j < i; j++) { float wv = Wrow[j]; wsn += wv * wv; }
    float scale = expf(dv) * rsqrtf(wsn);
    float* dst = g_wn1 + ((size_t)(f * D + i) * NHID + k) * D;
    for (int j = 0; j < D; j++) {
        float wv = (j < i) ? Wrow[j] : ((j == i) ? wdiag : 0.f);
        dst[j] = wv * scale;
    }
    g_c[(f * D + i) * NHID + k] = dv + Wrow[i] - 0.5f * logf(wsn);
}

// ---------------------------------------------------------------------------
__global__ void prep2(const float* __restrict__ W2, const float* __restrict__ d2) {
    int f = blockIdx.x >> 6;
    int oc = blockIdx.x & 63;
    int tid = threadIdx.x;
    const float* Wrow = W2 + (size_t)(f * D + oc) * H;
    __shared__ float red[128];
    float wsn = 0.f;
    int lim = (oc + 1) * NHID;
    for (int j = tid; j < lim; j += 128) {
        int jb = j >> 7;
        float wv = (jb == oc) ? expf(Wrow[j]) : Wrow[j];
        wsn += wv * wv;
    }
    red[tid] = wsn;
    __syncthreads();
    for (int s = 64; s > 0; s >>= 1) {
        if (tid < s) red[tid] += red[tid + s];
        __syncthreads();
    }
    wsn = red[0];
    float dv = d2[f * D + oc];
    float scale = expf(dv) * rsqrtf(wsn);
    for (int j = tid; j < H; j += 128) {
        int jb = j >> 7, k = j & 127;
        float wv = (jb < oc) ? Wrow[j] : ((jb == oc) ? expf(Wrow[j]) : 0.f);
        g_wn2[((size_t)(f * D + jb) * D + oc) * NHID + k] = wv * scale;
    }
    g_c[(f * D + oc) * NHID + tid] += dv + Wrow[oc * NHID + tid] - 0.5f * logf(wsn);
}

// ---------------------------------------------------------------------------
__device__ __forceinline__ void stage_w1(int g, float* dst, int tid) {
    int inx = g & 63;
    int jl4 = (inx >> 2) + 1;
    const float* src = g_wn1 + (size_t)g * NHID * D;
    #pragma unroll
    for (int q = tid; q < NHID * 16; q += NTH) {
        int k = q >> 4, c4 = q & 15;
        if (c4 < jl4)
            *(float4*)(dst + k * W1P + c4 * 4) =
                *(const float4*)(src + k * D + c4 * 4);
    }
}
__device__ __forceinline__ void stage_w2(int g, float* dst, int tid) {
    int inx = g & 63;
    const float* src = g_wn2 + (size_t)g * D * NHID;
    #pragma unroll
    for (int q = tid; q < D * 32; q += NTH) {
        int o = q >> 5, c4 = q & 31;
        if ((o | 7) >= inx)
            *(float4*)(dst + o * W2P + c4 * 4 + ((c4 >= 16) ? 4 : 0)) =
                *(const float4*)(src + o * NHID + c4 * 4);
    }
}
__device__ __forceinline__ void stage_bc(int g, float* dst,
                                         const float* __restrict__ b1g, int tid) {
    if (tid < 64) {
        int inx = g & 63, fl = g >> 6;
        if (tid < 32)
            *(float4*)(dst + tid * 4) =
                *(const float4*)(b1g + (size_t)fl * H + inx * NHID + tid * 4);
        else
            *(float4*)(dst + tid * 4) =
                *(const float4*)(g_c + (size_t)g * NHID + (tid - 32) * 4);
    }
}

// phase1 (h for block i1) + transcendental -> writes ts/ps target buffers
__device__ __forceinline__ void phase1_trans(
    int i1, const float* w1b, const float* bcb,
    float* tsn, float* psn, const float* xs, int kc, int rb)
{
    const float TWOLN2 = 1.3862943611198906f;
    ull a0[4] = {0ull,0ull,0ull,0ull}, a1[4] = {0ull,0ull,0ull,0ull};
    const float* wa = w1b + kc * W1P;
    const float* wb = w1b + (kc + 64) * W1P;
    #pragma unroll 4
    for (int j = 0; j <= i1; j += 4) {
        ulonglong2 wpa = *(const ulonglong2*)(wa + j);
        ulonglong2 wpb = *(const ulonglong2*)(wb + j);
        #pragma unroll
        for (int rr = 0; rr < 4; rr++) {
            ulonglong2 xp = *(const ulonglong2*)(xs + (rb + rr) * XP + j);
            a0[rr] = ffma2(xp.x, wpa.x, a0[rr]);
            a0[rr] = ffma2(xp.y, wpa.y, a0[rr]);
            a1[rr] = ffma2(xp.x, wpb.x, a1[rr]);
            a1[rr] = ffma2(xp.y, wpb.y, a1[rr]);
        }
    }
    float b1a = bcb[kc], b1b = bcb[kc + 64];
    float ca2 = bcb[128 + kc] + TWOLN2;
    float cb2 = bcb[128 + kc + 64] + TWOLN2;
    #pragma unroll
    for (int rr = 0; rr < 4; rr++) {
        int r = rb + rr;
        float l0, h0v, l1, h1v;
        upk2(a0[rr], l0, h0v);
        upk2(a1[rr], l1, h1v);
        float h0 = l0 + h0v + b1a;
        float h1 = l1 + h1v + b1b;
        float ah0 = fabsf(h0), ah1 = fabsf(h1);
        float E0 = __expf(-2.f * ah0);
        float E1 = __expf(-2.f * ah1);
        tsn[r * TSP + kc]      = copysignf(__fdividef(1.f - E0, 1.f + E0), h0);
        tsn[r * TSP + kc + 64] = copysignf(__fdividef(1.f - E1, 1.f + E1), h1);
        psn[r * TSP + kc]      = fmaf(-2.f, ah0 + __logf(1.f + E0), ca2);
        psn[r * TSP + kc + 64] = fmaf(-2.f, ah1 + __logf(1.f + E1), cb2);
    }
}

// ---------------------------------------------------------------------------
// Main fused kernel: software-pipelined slots. Slot ii runs phase2+lse(ii)
// (reading ts/ps[cur]) concurrently with phase1+trans(ii+1) (writing [nxt])
// and weight staging(ii+2). ONE barrier per slot.
// Phase2: 16 warps = 8 octets x 2 row-halves; lane = (row, k-half).
// ---------------------------------------------------------------------------
__global__ void __launch_bounds__(NTH, 1) bnaf_main(
    const float* __restrict__ x, const float* __restrict__ b1g,
    const float* __restrict__ b2, const float* __restrict__ gates,
    float* __restrict__ out)
{
    extern __shared__ float sm[];
    float* xs  = sm;                          // BM*XP       = 2176
    float* w1t = xs + BM * XP;                // 2*128*W1P   = 17408
    float* w2t = w1t + 2 * NHID * W1P;        // 2*64*W2P    = 17408
    float* bc  = w2t + 2 * D * W2P;           // 512
    float* tsb = bc + 512;                    // 2*BM*TSP    = 8448
    float* psb = tsb + 2 * BM * TSP;          // 2*BM*TSP    = 8448
    float* lds_s = psb + 2 * BM * TSP;        // BM

    const int tid = threadIdx.x;
    const int b0 = blockIdx.x * BM;

    // phase1 mapping
    const int kc = tid & 63;
    const int rb = (tid >> 6) * 4;
    // phase2 mapping: octet (SMSP-balanced), row-half, (row, k-half) lanes
    const int wid = tid >> 5, lane = tid & 31;
    const int p_ = wid & 7;
    const int oct = (p_ < 4) ? p_ : 11 - p_;
    const int rh = wid >> 3;
    const int row2 = rh * 16 + (lane >> 1);
    const int kh = lane & 1;
    const int oc0 = oct * 8;
    // logsumexp mapping
    const int lrow = tid >> 4, lsub = tid & 15;

    {   // load x tile
        int r = tid >> 4, c4 = tid & 15;
        *(float4*)(xs + r * XP + c4 * 4) =
            *(const float4*)(x + (size_t)(b0 + r) * D + c4 * 4);
    }
    if (tid < BM) lds_s[tid] = 0.f;

    for (int f = 0; f < NF; f++) {
        const int base = f * D;
        const bool gated = (f < NF - 1);
        const float gate = gated ? gates[f] : 0.f;
        const float sg = gated ? (1.f / (1.f + __expf(-gate))) : 0.f;
        const float spg = gated ? fast_sp(gate) : 0.f;

        ull yp[8];
        #pragma unroll
        for (int m = 0; m < 8; m++) yp[m] = 0ull;

        // ---- prologue: stage w1(0),w1(1),w2(0),bc(0),bc(1); then phase1(0)
        stage_w1(base + 0, w1t, tid);
        stage_w1(base + 1, w1t + NHID * W1P, tid);
        stage_w2(base + 0, w2t, tid);
        stage_bc(base + 0, bc, b1g, tid);
        stage_bc(base + 1, bc + 256, b1g, tid);
        __syncthreads();
        phase1_trans(0, w1t, bc, tsb, psb, xs, kc, rb);
        __syncthreads();

        for (int ii = 0; ii < D; ii++) {
            const int cur = ii & 1, nxt = cur ^ 1;

            // stage ahead (issue LDGs early; buffers free by parity)
            if (ii < D - 2) {
                stage_w1(base + ii + 2, w1t + cur * (NHID * W1P), tid);
                stage_bc(base + ii + 2, bc + cur * 256, b1g, tid);
            }
            if (ii < D - 1)
                stage_w2(base + ii + 1, w2t + nxt * (D * W2P), tid);

            // phase1(ii+1) -> ts/ps[nxt] (independent of phase2 below)
            if (ii < D - 1)
                phase1_trans(ii + 1, w1t + nxt * (NHID * W1P), bc + nxt * 256,
                             tsb + nxt * (BM * TSP), psb + nxt * (BM * TSP),
                             xs, kc, rb);

            // phase2(ii): reads ts[cur], w2[cur]; exact octet skip
            if (oc0 + 7 >= ii) {
                const float* tr = tsb + cur * (BM * TSP) + row2 * TSP + kh * 64;
                const float* uq = w2t + cur * (D * W2P) + oc0 * W2P + kh * 68;
                #pragma unroll 4
                for (int k = 0; k < 64; k += 4) {
                    ulonglong2 tp = *(const ulonglong2*)(tr + k);
                    #pragma unroll
                    for (int m = 0; m < 8; m++) {
                        ulonglong2 q = *(const ulonglong2*)(uq + m * W2P + k);
                        yp[m] = ffma2(tp.x, q.x, yp[m]);
                        yp[m] = ffma2(tp.y, q.y, yp[m]);
                    }
                }
            }

            // lse(ii): reads ps[cur]
            {
                const float* pr = psb + cur * (BM * TSP) + lrow * TSP + lsub * 8;
                float4 v0 = *(const float4*)(pr);
                float4 v1 = *(const float4*)(pr + 4);
                float mx = fmaxf(fmaxf(fmaxf(v0.x, v0.y), fmaxf(v0.z, v0.w)),
                                 fmaxf(fmaxf(v1.x, v1.y), fmaxf(v1.z, v1.w)));
                #pragma unroll
                for (int o2 = 8; o2 > 0; o2 >>= 1)
                    mx = fmaxf(mx, __shfl_xor_sync(0xffffffffu, mx, o2));
                float se = __expf(v0.x - mx) + __expf(v0.y - mx)
                         + __expf(v0.z - mx) + __expf(v0.w - mx)
                         + __expf(v1.x - mx) + __expf(v1.y - mx)
                         + __expf(v1.z - mx) + __expf(v1.w - mx);
                #pragma unroll
                for (int o2 = 8; o2 > 0; o2 >>= 1)
                    se += __shfl_xor_sync(0xffffffffu, se, o2);
                if (lsub == 0) {
                    float gg = mx + __logf(se);
                    lds_s[lrow] += gated ? (fast_sp(gg + gate) - spg) : gg;
                }
            }
            __syncthreads();
        }

        // ---- combine k-half partials, then gate/reverse or final output
        float ysum[8];
        #pragma unroll
        for (int m = 0; m < 8; m++) {
            float lo, hi;
            upk2(yp[m], lo, hi);
            float p = lo + hi;
            p += __shfl_xor_sync(0xffffffffu, p, 1);
            ysum[m] = p + b2[f * D + oc0 + m];
        }
        if (gated) {
            float xo[8];
            #pragma unroll
            for (int m = 0; m < 8; m++)
                xo[m] = sg * ysum[m] + (1.f - sg) * xs[row2 * XP + oc0 + m];
            __syncthreads();
            #pragma unroll
            for (int m = 0; m < 8; m++)
                xs[row2 * XP + 63 - (oc0 + m)] = xo[m];
            // visibility to next flow's phase1 via the prologue barrier
        } else {
            if (kh == 0) {
                #pragma unroll
                for (int m = 0; m < 8; m++)
                    out[(size_t)(b0 + row2) * D + oc0 + m] = ysum[m];
            }
        }
    }

    if (tid < BM) out[(size_t)BATCH * D + b0 + tid] = lds_s[tid];
}

static const int SMEM_BYTES =
    (BM * XP + 2 * NHID * W1P + 2 * D * W2P + 512 + 4 * BM * TSP + BM) * 4;

extern "C" void kernel_launch(void* const* d_in, const int* in_sizes, int n_in,
                              void* d_out, int out_size) {
    const float* x  = (const float*)d_in[0];
    const float* W1 = (const float*)d_in[1];
    const float* d1 = (const float*)d_in[2];
    const float* b1 = (const float*)d_in[3];
    const float* W2 = (const float*)d_in[4];
    const float* d2 = (const float*)d_in[5];
    const float* b2 = (const float*)d_in[6];
    const float* gates = (const float*)d_in[7];
    float* out = (float*)d_out;

    prep1<<<(NF * H + 255) / 256, 256>>>(W1, d1);
    prep2<<<NF * D, 128>>>(W2, d2);

    cudaFuncSetAttribute(bnaf_main, cudaFuncAttributeMaxDynamicSharedMemorySize, SMEM_BYTES);
    bnaf_main<<<BATCH / BM, NTH, SMEM_BYTES>>>(x, b1, b2, gates, out);
}